// round 13
// baseline (speedup 1.0000x reference)
#include <cuda_runtime.h>
#include <cstdint>

#define TPB 256
#define SAS 20
#define SBSN 72
#define ABUF 1280          // 64*20 words per stage
#define BBUF 1280          // max(16*72=1152, 64*20=1280)

// B=4, U=64, V=256, DIM=768, CODE=384, INNER=512, HEADS=8, HD=64

struct Params {
    const float *recv, *codes, *send;
    const float *lnrg, *lnrb, *lnsg, *lnsb;
    const float *Wq, *bq, *Wmq, *Wk, *bk, *Wmk;
    const float *Wv, *bv, *Wmv, *We, *be, *Wme, *gamma;
    float* out;
    int nb;
};

// ---------------- Scratch (device globals; no allocs) ----------------
__device__ __align__(16) float g_r  [256 * 768];
__device__ __align__(16) float g_s  [1024 * 768];
__device__ __align__(16) float g_rq [256 * 768];
__device__ __align__(16) float g_mqp[2 * 196608];
__device__ __align__(16) float g_mkp[2 * 196608];
__device__ __align__(16) float g_mvp[2 * 196608];
__device__ __align__(16) float g_mep[2 * 131072];
__device__ __align__(16) float g_q  [256 * 512];
__device__ __align__(16) float g_qbk[256 * 8];
__device__ __align__(16) float g_Ak [4 * 512 * 768];
__device__ __align__(16) float g_w  [4 * 512 * 256];
__device__ __align__(16) float g_Tm [8 * 256 * 768];
__device__ __align__(16) float g_msg[256 * 512];
#define QP 131072
#define WP 524288
#define OP 196608
__device__ __align__(16) float g_qp[8 * QP];
__device__ __align__(16) float g_wp[3 * WP];

__device__ unsigned g_barcnt = 0;
__device__ unsigned g_bargen = 0;

__device__ __forceinline__ void grid_bar(int nb) {
    __syncthreads();
    if (threadIdx.x == 0) {
        __threadfence();
        unsigned gen = *(volatile unsigned*)&g_bargen;
        unsigned t = atomicAdd(&g_barcnt, 1u);
        if (t == (unsigned)(nb - 1)) {
            atomicExch(&g_barcnt, 0u);
            __threadfence();
            atomicExch(&g_bargen, gen + 1u);
        } else {
            while (*(volatile unsigned*)&g_bargen == gen) { __nanosleep(32); }
        }
        __threadfence();
    }
    __syncthreads();
}

// ---------------- mma + cp.async helpers ----------------
__device__ __forceinline__ void mma8(float* c, const uint32_t* a, const uint32_t* b) {
    asm volatile(
        "mma.sync.aligned.m16n8k8.row.col.f32.tf32.tf32.f32 "
        "{%0,%1,%2,%3}, {%4,%5,%6,%7}, {%8,%9}, {%0,%1,%2,%3};"
        : "+f"(c[0]), "+f"(c[1]), "+f"(c[2]), "+f"(c[3])
        : "r"(a[0]), "r"(a[1]), "r"(a[2]), "r"(a[3]), "r"(b[0]), "r"(b[1]));
}
__device__ __forceinline__ uint32_t tfr(uint32_t raw) {
    uint32_t u;
    asm("cvt.rna.tf32.f32 %0, %1;" : "=r"(u) : "f"(__uint_as_float(raw)));
    return u;
}
__device__ __forceinline__ void cp16(uint32_t dst, const float* src) {
    asm volatile("cp.async.cg.shared.global [%0], [%1], 16;\n"
                 :: "r"(dst), "l"(src) : "memory");
}
__device__ __forceinline__ void cp_commit() {
    asm volatile("cp.async.commit_group;\n" ::: "memory");
}
__device__ __forceinline__ void cp_wait2() {
    asm volatile("cp.async.wait_group 2;\n" ::: "memory");
}
__device__ __forceinline__ float4 ld4(const float* p) { return *(const float4*)p; }

// ------- block 64x64 tf32 GEMM, 4-stage cp.async pipeline (R10-verified) -------
template<bool BT, class LA, class LB, class EP>
__device__ __forceinline__ void gemm_cp(int K, uint32_t* sA, uint32_t* sB,
                                        uint32_t saA, uint32_t saB,
                                        LA la, LB lb, EP ep) {
    const int tid = threadIdx.x;
    const int l = tid & 31, g = l >> 2, t = l & 3;
    const int wid = tid >> 5;
    const int wm0 = (wid & 1) * 32, wn0 = (wid >> 1) * 16;
    const int am = tid >> 2, ak = (tid & 3) * 4;
    const int bk = tid >> 4, bn = (tid & 15) * 4;
    const int btn = tid >> 2, btk = (tid & 3) * 4;
    const int ns = K / 16;

    const uint32_t dA = saA + (uint32_t)(am * SAS + ak) * 4u;
    const uint32_t dB = BT ? saB + (uint32_t)(btn * SAS + btk) * 4u
                           : saB + (uint32_t)(bk * SBSN + bn) * 4u;

    auto issue = [&](int s) {
        int buf = s & 3;
        int k0 = s * 16;
        cp16(dA + buf * (ABUF * 4), la(am, k0 + ak));
        cp16(dB + buf * (BBUF * 4), BT ? lb(btn, k0 + btk) : lb(k0 + bk, bn));
        cp_commit();
    };

    float acc[2][2][4];
    #pragma unroll
    for (int i = 0; i < 2; i++)
        #pragma unroll
        for (int j = 0; j < 2; j++)
            #pragma unroll
            for (int e = 0; e < 4; e++) acc[i][j][e] = 0.f;

    issue(0); issue(1); issue(2);
    cp_wait2();
    __syncthreads();

    for (int s = 0; s < ns; s++) {
        if (s + 3 < ns) issue(s + 3); else cp_commit();
        const uint32_t* __restrict__ A = sA + (s & 3) * ABUF;
        const uint32_t* __restrict__ B = sB + (s & 3) * BBUF;
        #pragma unroll
        for (int kk = 0; kk < 16; kk += 8) {
            uint32_t af[2][4], bf[2][2];
            #pragma unroll
            for (int mi = 0; mi < 2; mi++) {
                int mb = wm0 + mi * 16;
                af[mi][0] = tfr(A[(mb + g) * SAS + kk + t]);
                af[mi][1] = tfr(A[(mb + 8 + g) * SAS + kk + t]);
                af[mi][2] = tfr(A[(mb + g) * SAS + kk + t + 4]);
                af[mi][3] = tfr(A[(mb + 8 + g) * SAS + kk + t + 4]);
            }
            #pragma unroll
            for (int ni = 0; ni < 2; ni++) {
                int nn = wn0 + ni * 8 + g;
                if (BT) {
                    bf[ni][0] = tfr(B[nn * SAS + kk + t]);
                    bf[ni][1] = tfr(B[nn * SAS + kk + t + 4]);
                } else {
                    bf[ni][0] = tfr(B[(kk + t) * SBSN + nn]);
                    bf[ni][1] = tfr(B[(kk + t + 4) * SBSN + nn]);
                }
            }
            #pragma unroll
            for (int mi = 0; mi < 2; mi++)
                #pragma unroll
                for (int ni = 0; ni < 2; ni++)
                    mma8(acc[mi][ni], af[mi], bf[ni]);
        }
        cp_wait2();
        __syncthreads();
    }

    #pragma unroll
    for (int mi = 0; mi < 2; mi++)
        #pragma unroll
        for (int ni = 0; ni < 2; ni++) {
            int r = wm0 + mi * 16 + g, c = wn0 + ni * 8 + 2 * t;
            ep(r,     c,     acc[mi][ni][0]);
            ep(r,     c + 1, acc[mi][ni][1]);
            ep(r + 8, c,     acc[mi][ni][2]);
            ep(r + 8, c + 1, acc[mi][ni][3]);
        }
}

// ---------------- warp LayerNorm over a 768-row ----------------
__device__ __forceinline__ void ln_row(const float* __restrict__ x,
                                       const float* __restrict__ g,
                                       const float* __restrict__ b,
                                       float* __restrict__ o) {
    int lane = threadIdx.x & 31;
    float v[24];
    float s = 0.f, q = 0.f;
    #pragma unroll
    for (int i = 0; i < 24; i++) {
        v[i] = x[lane + 32 * i];
        s += v[i];
        q += v[i] * v[i];
    }
    #pragma unroll
    for (int off = 16; off; off >>= 1) {
        s += __shfl_xor_sync(0xffffffffu, s, off);
        q += __shfl_xor_sync(0xffffffffu, q, off);
    }
    float mu  = s * (1.f / 768.f);
    float inv = rsqrtf(q * (1.f / 768.f) - mu * mu + 1e-5f);
    #pragma unroll
    for (int i = 0; i < 24; i++) {
        int idx = lane + 32 * i;
        o[idx] = (v[i] - mu) * inv * g[idx] + b[idx];
    }
}

// ---------------- The single persistent kernel (4 blocks/SM) ----------------
__global__ void __launch_bounds__(TPB, 4) fused_kernel(Params P) {
    __shared__ __align__(16) uint32_t sA[4 * ABUF];
    __shared__ __align__(16) uint32_t sB[4 * BBUF];
    const uint32_t saA = (uint32_t)__cvta_generic_to_shared(sA);
    const uint32_t saB = (uint32_t)__cvta_generic_to_shared(sB);
    const int nb = P.nb;
    const int bid = blockIdx.x;
    const int wglob = bid * 8 + (threadIdx.x >> 5);
    const int nwarp = nb * 8;
    const int lane32 = threadIdx.x & 31;
    const int nth = nwarp * 32;
    const int gt = wglob * 32 + lane32;

    // ---- S0: LayerNorms ----
    for (int r = wglob; r < 1280; r += nwarp) {
        if (r < 256) ln_row(P.recv + r * 768, P.lnrg, P.lnrb, g_r + r * 768);
        else {
            int rr = r - 256;
            ln_row(P.send + rr * 768, P.lnsg, P.lnsb, g_s + rr * 768);
        }
    }
    grid_bar(nb);

    // ---- S1: mq GEMM only (critical path), K split x2: 96 tiles ----
    for (int tt = bid; tt < 96; tt += nb) {
        int kp = tt / 48, lt = tt % 48;
        int m0 = (lt & 3) * 64, n0 = (lt >> 2) * 64, kb = kp * 192;
        float* O = g_mqp + kp * 196608;
        gemm_cp<false>(192, sA, sB, saA, saB,
            [&](int m, int k) { return &P.codes[(m0 + m) * 384 + kb + k]; },
            [&](int k, int n) { return &P.Wmq[(kb + k) * 768 + n0 + n]; },
            [&](int m, int n, float a) { O[(long)(m0 + m) * 768 + n0 + n] = a; });
    }
    grid_bar(nb);

    // ---- S1b: rq = r * (1 + mqp0 + mqp1) ----
    for (int i = gt; i < 49152; i += nth) {
        long idx = (long)i * 4;
        float4 a = ld4(&g_mqp[idx]), b = ld4(&g_mqp[196608 + idx]), r = ld4(&g_r[idx]);
        float4 o;
        o.x = r.x * (1.f + a.x + b.x); o.y = r.y * (1.f + a.y + b.y);
        o.z = r.z * (1.f + a.z + b.z); o.w = r.w * (1.f + a.w + b.w);
        *(float4*)&g_rq[idx] = o;
    }
    grid_bar(nb);

    // ---- S2: q partials (256) + mk (96) + mv (96) + me (64) = 512 tiles ----
    for (int tt = bid; tt < 512; tt += nb) {
        if (tt < 256) {
            int kp = tt >> 5, lt = tt & 31;
            int m0 = (lt & 3) * 64, n0 = (lt >> 2) * 64, kb = kp * 96;
            gemm_cp<false>(96, sA, sB, saA, saB,
                [&](int m, int k) { return &g_rq[(m0 + m) * 768 + kb + k]; },
                [&](int k, int n) { return &P.Wq[(kb + k) * 512 + n0 + n]; },
                [&](int m, int n, float a) { g_qp[kp * QP + (m0 + m) * 512 + n0 + n] = a; });
        } else if (tt < 448) {
            int r = tt - 256;
            int sel = r / 96;                    // 0: mk, 1: mv
            int rr = r % 96;
            int kp = rr / 48, lt = rr % 48;
            const float* W = sel == 0 ? P.Wmk : P.Wmv;
            float* O = (sel == 0 ? g_mkp : g_mvp) + kp * 196608;
            int m0 = (lt & 3) * 64, n0 = (lt >> 2) * 64, kb = kp * 192;
            gemm_cp<false>(192, sA, sB, saA, saB,
                [&](int m, int k) { return &P.codes[(m0 + m) * 384 + kb + k]; },
                [&](int k, int n) { return &W[(kb + k) * 768 + n0 + n]; },
                [&](int m, int n, float a) { O[(long)(m0 + m) * 768 + n0 + n] = a; });
        } else {
            int r = tt - 448;
            int kp = r / 32, lt = r % 32;
            float* O = g_mep + kp * 131072;
            int m0 = (lt & 3) * 64, n0 = (lt >> 2) * 64, kb = kp * 192;
            gemm_cp<false>(192, sA, sB, saA, saB,
                [&](int m, int k) { return &P.codes[(m0 + m) * 384 + kb + k]; },
                [&](int k, int n) { return &P.Wme[(kb + k) * 512 + n0 + n]; },
                [&](int m, int n, float a) { O[(long)(m0 + m) * 512 + n0 + n] = a; });
        }
    }
    grid_bar(nb);

    // ---- S2b: q = sum(8 partials)+bq ; qbk = q_h . bk_h ----
    for (int w = wglob; w < 2048; w += nwarp) {
        int bu = w >> 3, h = w & 7;
        int base = bu * 512 + h * 64;
        int c0 = h * 64 + lane32, c1 = c0 + 32;
        float q0 = P.bq[c0], q1 = P.bq[c1];
        #pragma unroll
        for (int p = 0; p < 8; p++) {
            q0 += g_qp[p * QP + base + lane32];
            q1 += g_qp[p * QP + base + lane32 + 32];
        }
        g_q[base + lane32] = q0;
        g_q[base + lane32 + 32] = q1;
        float s = q0 * P.bk[c0] + q1 * P.bk[c1];
        #pragma unroll
        for (int off = 16; off; off >>= 1) s += __shfl_xor_sync(0xffffffffu, s, off);
        if (lane32 == 0) g_qbk[bu * 8 + h] = s;
    }
    grid_bar(nb);

    // ---- S3: Ak = (Wk_h^T q_h)*(1+mk0+mk1)  per-head NT, K=64: 384 tiles ----
    for (int tt = bid; tt < 384; tt += nb) {
        int h = tt / 48, lt = tt % 48;
        int m0 = (lt & 3) * 64, n0 = (lt >> 2) * 64;
        gemm_cp<true>(64, sA, sB, saA, saB,
            [&](int m, int k) { return &g_q[(m0 + m) * 512 + h * 64 + k]; },
            [&](int n, int k) { return &P.Wk[(n0 + n) * 512 + h * 64 + k]; },
            [&](int m, int n, float a) {
                int mg = m0 + m; int b = mg >> 6, u = mg & 63;
                long mi = (long)mg * 768 + n0 + n;
                g_Ak[b * 393216 + (h * 64 + u) * 768 + n0 + n] =
                    a * (1.f + g_mkp[mi] + g_mkp[196608 + mi]);
            });
    }
    grid_bar(nb);

    // ---- S4: score partials, K split x3 (K=256): 384 tiles ----
    for (int tt = bid; tt < 384; tt += nb) {
        int kp = tt >> 7, lt = tt & 127;
        int b = lt >> 5, l2 = lt & 31;
        int m0 = (l2 & 7) * 64, n0 = (l2 >> 3) * 64, kb = kp * 256;
        gemm_cp<true>(256, sA, sB, saA, saB,
            [&](int m, int k) { return &g_Ak[b * 393216 + (m0 + m) * 768 + kb + k]; },
            [&](int n, int k) { return &g_s[(b * 256 + n0 + n) * 768 + kb + k]; },
            [&](int m, int n, float a) {
                g_wp[kp * WP + b * 131072 + (m0 + m) * 256 + n0 + n] = a;
            });
    }
    grid_bar(nb);

    // ---- S5: softmax( (wp0+wp1+wp2+qbk)/8 ) -> g_w ----
    for (int r = wglob; r < 2048; r += nwarp) {
        int b = r >> 9, mg = r & 511;
        int h = mg >> 6, u = mg & 63;
        float qb = g_qbk[(b * 64 + u) * 8 + h];
        long base = (long)b * 131072 + (long)mg * 256;
        float v[8], mx = -1e30f;
        #pragma unroll
        for (int i = 0; i < 8; i++) {
            long idx = base + lane32 + 32 * i;
            v[i] = (g_wp[idx] + g_wp[WP + idx] + g_wp[2 * WP + idx] + qb) * 0.125f;
            mx = fmaxf(mx, v[i]);
        }
        #pragma unroll
        for (int off = 16; off; off >>= 1) mx = fmaxf(mx, __shfl_xor_sync(0xffffffffu, mx, off));
        float sm = 0.f;
        #pragma unroll
        for (int i = 0; i < 8; i++) { v[i] = expf(v[i] - mx); sm += v[i]; }
        #pragma unroll
        for (int off = 16; off; off >>= 1) sm += __shfl_xor_sync(0xffffffffu, sm, off);
        float inv = 1.f / sm;
        #pragma unroll
        for (int i = 0; i < 8; i++) g_w[base + lane32 + 32 * i] = v[i] * inv;
    }
    grid_bar(nb);

    // ---- S6: Tm = (w @ s)*(1+mv0+mv1), per-head remap: 384 tiles, K=256 ----
    for (int tt = bid; tt < 384; tt += nb) {
        int b = tt / 96, lt = tt % 96;
        int m0 = (lt & 7) * 64, n0 = (lt >> 3) * 64;
        gemm_cp<false>(256, sA, sB, saA, saB,
            [&](int m, int k) { return &g_w[b * 131072 + (m0 + m) * 256 + k]; },
            [&](int k, int n) { return &g_s[(b * 256 + k) * 768 + n0 + n]; },
            [&](int m, int n, float a) {
                int mg = m0 + m; int h = mg >> 6, u = mg & 63; int bu = b * 64 + u;
                long mi = (long)bu * 768 + n0 + n;
                g_Tm[(h * 256 + bu) * 768 + n0 + n] =
                    a * (1.f + g_mvp[mi] + g_mvp[196608 + mi]);
            });
    }
    grid_bar(nb);

    // ---- S7: msg partials = Tm_h @ Wv_h, K split x8 (K=96): 256 tiles ----
    for (int tt = bid; tt < 256; tt += nb) {
        int kp = tt >> 5, lt = tt & 31;
        int h = lt >> 2, m0 = (lt & 3) * 64, kb = kp * 96;
        gemm_cp<false>(96, sA, sB, saA, saB,
            [&](int m, int k) { return &g_Tm[(h * 256 + m0 + m) * 768 + kb + k]; },
            [&](int k, int n) { return &P.Wv[(kb + k) * 512 + h * 64 + n]; },
            [&](int m, int n, float a) {
                g_qp[kp * QP + (m0 + m) * 512 + h * 64 + n] = a;
            });
    }
    grid_bar(nb);

    // ---- S7b: msg = (sum(8 partials)+bv)*(1+me0+me1) ----
    for (int i = gt; i < 32768; i += nth) {
        long idx = (long)i * 4;
        int c = (int)(idx & 511);
        float4 acc = ld4(&P.bv[c]);
        #pragma unroll
        for (int p = 0; p < 8; p++) {
            float4 v = ld4(&g_qp[p * QP + idx]);
            acc.x += v.x; acc.y += v.y; acc.z += v.z; acc.w += v.w;
        }
        float4 m0 = ld4(&g_mep[idx]), m1 = ld4(&g_mep[131072 + idx]);
        float4 o;
        o.x = acc.x * (1.f + m0.x + m1.x); o.y = acc.y * (1.f + m0.y + m1.y);
        o.z = acc.z * (1.f + m0.z + m1.z); o.w = acc.w * (1.f + m0.w + m1.w);
        *(float4*)&g_msg[idx] = o;
    }
    grid_bar(nb);

    // ---- S8: out partials = msg @ We, K split x8 (K=64): 384 tiles ----
    for (int tt = bid; tt < 384; tt += nb) {
        int kp = tt / 48, lt = tt % 48;
        int m0 = (lt & 3) * 64, n0 = (lt >> 2) * 64, kb = kp * 64;
        gemm_cp<false>(64, sA, sB, saA, saB,
            [&](int m, int k) { return &g_msg[(m0 + m) * 512 + kb + k]; },
            [&](int k, int n) { return &P.We[(kb + k) * 768 + n0 + n]; },
            [&](int m, int n, float a) {
                g_wp[kp * OP + (m0 + m) * 768 + n0 + n] = a;
            });
    }
    grid_bar(nb);

    // ---- S9: out = recv + (sum(8 partials)+be)*gamma ----
    for (int i = gt; i < 49152; i += nth) {
        long idx = (long)i * 4;
        int c = (int)(idx % 768);
        float4 acc = ld4(&P.be[c]);
        #pragma unroll
        for (int p = 0; p < 8; p++) {
            float4 v = ld4(&g_wp[p * OP + idx]);
            acc.x += v.x; acc.y += v.y; acc.z += v.z; acc.w += v.w;
        }
        float4 ga = ld4(&P.gamma[c]);
        float4 rv = ld4(&P.recv[idx]);
        float4 o;
        o.x = rv.x + acc.x * ga.x; o.y = rv.y + acc.y * ga.y;
        o.z = rv.z + acc.z * ga.z; o.w = rv.w + acc.w * ga.w;
        *(float4*)&P.out[idx] = o;
    }
}

// ---------------- Host launcher ----------------
extern "C" void kernel_launch(void* const* d_in, const int* in_sizes, int n_in,
                              void* d_out, int out_size) {
    (void)in_sizes; (void)n_in; (void)out_size;
    Params P;
    P.recv  = (const float*)d_in[0];
    P.codes = (const float*)d_in[1];
    P.send  = (const float*)d_in[2];
    P.lnrg  = (const float*)d_in[3];
    P.lnrb  = (const float*)d_in[4];
    P.lnsg  = (const float*)d_in[5];
    P.lnsb  = (const float*)d_in[6];
    P.Wq  = (const float*)d_in[7];
    P.bq  = (const float*)d_in[8];
    P.Wmq = (const float*)d_in[9];
    P.Wk  = (const float*)d_in[10];
    P.bk  = (const float*)d_in[11];
    P.Wmk = (const float*)d_in[12];
    P.Wv  = (const float*)d_in[13];
    P.bv  = (const float*)d_in[14];
    P.Wmv = (const float*)d_in[15];
    P.We  = (const float*)d_in[16];
    P.be  = (const float*)d_in[17];
    P.Wme = (const float*)d_in[18];
    P.gamma = (const float*)d_in[19];
    P.out = (float*)d_out;

    int occ = 0;
    cudaOccupancyMaxActiveBlocksPerMultiprocessor(&occ, fused_kernel, TPB, 0);
    if (occ < 1) occ = 1;
    int dev = 0;
    cudaGetDevice(&dev);
    int sms = 0;
    cudaDeviceGetAttribute(&sms, cudaDevAttrMultiProcessorCount, dev);
    if (sms < 1) sms = 1;
    int nb = occ * sms;
    if (nb > 1024) nb = 1024;
    P.nb = nb;

    fused_kernel<<<nb, TPB>>>(P);
}

// round 14
// speedup vs baseline: 1.0366x; 1.0366x over previous
#include <cuda_runtime.h>
#include <cstdint>

#define TPB 256
#define SAS 20
#define SBSN 72
#define ABUFW (128 * SAS)        // 2560 words per A stage buf
#define BBUFW 1280               // max(16*72=1152, 64*20=1280)
#define ASPAN (4 * ABUFW)        // 10240 words
#define DYNW  (ASPAN + 4 * BBUFW)  // 15360 words
#define DYNSMEM (DYNW * 4)         // 61440 bytes

// B=4, U=64, V=256, DIM=768, CODE=384, INNER=512, HEADS=8, HD=64

struct Params {
    const float *recv, *codes, *send;
    const float *lnrg, *lnrb, *lnsg, *lnsb;
    const float *Wq, *bq, *Wmq, *Wk, *bk, *Wmk;
    const float *Wv, *bv, *Wmv, *We, *be, *Wme, *gamma;
    float* out;
    int nb;
};

// ---------------- Scratch (device globals; no allocs) ----------------
__device__ __align__(16) float g_r  [256 * 768];
__device__ __align__(16) float g_s  [1024 * 768];
__device__ __align__(16) float g_rq [256 * 768];
__device__ __align__(16) float g_mqp[2 * 196608];
__device__ __align__(16) float g_mkp[2 * 196608];
__device__ __align__(16) float g_mvp[2 * 196608];
__device__ __align__(16) float g_mep[2 * 131072];
__device__ __align__(16) float g_q  [256 * 512];
__device__ __align__(16) float g_qbk[256 * 8];
__device__ __align__(16) float g_Ak [4 * 512 * 768];
__device__ __align__(16) float g_w  [4 * 512 * 256];
__device__ __align__(16) float g_Tm [8 * 256 * 768];
__device__ __align__(16) float g_msg[256 * 512];
#define QP 131072
#define WP 524288
#define OP 196608
__device__ __align__(16) float g_qp[8 * QP];
__device__ __align__(16) float g_wp[3 * WP];

__device__ unsigned g_barcnt = 0;
__device__ unsigned g_bargen = 0;

__device__ __forceinline__ void grid_bar(int nb) {
    __syncthreads();
    if (threadIdx.x == 0) {
        __threadfence();
        unsigned gen = *(volatile unsigned*)&g_bargen;
        unsigned t = atomicAdd(&g_barcnt, 1u);
        if (t == (unsigned)(nb - 1)) {
            atomicExch(&g_barcnt, 0u);
            __threadfence();
            atomicExch(&g_bargen, gen + 1u);
        } else {
            while (*(volatile unsigned*)&g_bargen == gen) { __nanosleep(32); }
        }
        __threadfence();
    }
    __syncthreads();
}

// ---------------- mma + cp.async helpers ----------------
__device__ __forceinline__ void mma8(float* c, const uint32_t* a, const uint32_t* b) {
    asm volatile(
        "mma.sync.aligned.m16n8k8.row.col.f32.tf32.tf32.f32 "
        "{%0,%1,%2,%3}, {%4,%5,%6,%7}, {%8,%9}, {%0,%1,%2,%3};"
        : "+f"(c[0]), "+f"(c[1]), "+f"(c[2]), "+f"(c[3])
        : "r"(a[0]), "r"(a[1]), "r"(a[2]), "r"(a[3]), "r"(b[0]), "r"(b[1]));
}
__device__ __forceinline__ uint32_t tfr(uint32_t raw) {
    uint32_t u;
    asm("cvt.rna.tf32.f32 %0, %1;" : "=r"(u) : "f"(__uint_as_float(raw)));
    return u;
}
__device__ __forceinline__ void cp16(uint32_t dst, const float* src) {
    asm volatile("cp.async.cg.shared.global [%0], [%1], 16;\n"
                 :: "r"(dst), "l"(src) : "memory");
}
__device__ __forceinline__ void cp_commit() {
    asm volatile("cp.async.commit_group;\n" ::: "memory");
}
__device__ __forceinline__ void cp_wait2() {
    asm volatile("cp.async.wait_group 2;\n" ::: "memory");
}
__device__ __forceinline__ float4 ld4(const float* p) { return *(const float4*)p; }

// ------- block 128x64 tf32 GEMM, warp tile 32x32, 4-stage cp.async pipeline ----
// C(m,n) = sum_k A(m,k)*B(k,n); m in [0,128), n in [0,64); K%16==0, K>=64.
// la(m,k)->ptr A(m, k..k+3) for m in [0,128).
// BT=false: lb(k,n)->ptr B(k, n..n+3); BT=true: lb(n,k)->ptr B(n-th row, k..k+3).
template<bool BT, class LA, class LB, class EP>
__device__ __forceinline__ void gemm_cp(int K, uint32_t* sm, uint32_t saBase,
                                        LA la, LB lb, EP ep) {
    const int tid = threadIdx.x;
    const int l = tid & 31, g = l >> 2, t = l & 3;
    const int wid = tid >> 5;
    const int wm0 = (wid >> 1) * 32, wn0 = (wid & 1) * 32;
    const int ar = tid >> 2, ac = (tid & 3) * 4;       // A fill: rows ar, ar+64
    const int bk = tid >> 4, bn = (tid & 15) * 4;      // B NN fill
    const int btn = tid >> 2, btk = (tid & 3) * 4;     // B NT fill
    const int ns = K / 16;

    const uint32_t dA0 = saBase + (uint32_t)(ar * SAS + ac) * 4u;
    const uint32_t dA1 = dA0 + 64u * SAS * 4u;
    const uint32_t bbase = saBase + (uint32_t)ASPAN * 4u;
    const uint32_t dB = BT ? bbase + (uint32_t)(btn * SAS + btk) * 4u
                           : bbase + (uint32_t)(bk * SBSN + bn) * 4u;

    auto issue = [&](int s) {
        int buf = s & 3;
        int k0 = s * 16;
        uint32_t ao = (uint32_t)buf * (ABUFW * 4u);
        uint32_t bo = (uint32_t)buf * (BBUFW * 4u);
        cp16(dA0 + ao, la(ar, k0 + ac));
        cp16(dA1 + ao, la(ar + 64, k0 + ac));
        cp16(dB + bo, BT ? lb(btn, k0 + btk) : lb(k0 + bk, bn));
        cp_commit();
    };

    float acc[2][4][4];
    #pragma unroll
    for (int i = 0; i < 2; i++)
        #pragma unroll
        for (int j = 0; j < 4; j++)
            #pragma unroll
            for (int e = 0; e < 4; e++) acc[i][j][e] = 0.f;

    issue(0); issue(1); issue(2);
    cp_wait2();
    __syncthreads();

    for (int s = 0; s < ns; s++) {
        if (s + 3 < ns) issue(s + 3); else cp_commit();
        const uint32_t* __restrict__ A = sm + (s & 3) * ABUFW;
        const uint32_t* __restrict__ B = sm + ASPAN + (s & 3) * BBUFW;
        #pragma unroll
        for (int kk = 0; kk < 16; kk += 8) {
            uint32_t af[2][4], bf[4][2];
            #pragma unroll
            for (int mi = 0; mi < 2; mi++) {
                int mb = wm0 + mi * 16;
                af[mi][0] = tfr(A[(mb + g) * SAS + kk + t]);
                af[mi][1] = tfr(A[(mb + 8 + g) * SAS + kk + t]);
                af[mi][2] = tfr(A[(mb + g) * SAS + kk + t + 4]);
                af[mi][3] = tfr(A[(mb + 8 + g) * SAS + kk + t + 4]);
            }
            #pragma unroll
            for (int nj = 0; nj < 4; nj++) {
                int nn = wn0 + nj * 8 + g;
                if (BT) {
                    bf[nj][0] = tfr(B[nn * SAS + kk + t]);
                    bf[nj][1] = tfr(B[nn * SAS + kk + t + 4]);
                } else {
                    bf[nj][0] = tfr(B[(kk + t) * SBSN + nn]);
                    bf[nj][1] = tfr(B[(kk + t + 4) * SBSN + nn]);
                }
            }
            #pragma unroll
            for (int mi = 0; mi < 2; mi++)
                #pragma unroll
                for (int nj = 0; nj < 4; nj++)
                    mma8(acc[mi][nj], af[mi], bf[nj]);
        }
        cp_wait2();
        __syncthreads();
    }

    #pragma unroll
    for (int mi = 0; mi < 2; mi++)
        #pragma unroll
        for (int nj = 0; nj < 4; nj++) {
            int r = wm0 + mi * 16 + g, c = wn0 + nj * 8 + 2 * t;
            ep(r,     c,     acc[mi][nj][0]);
            ep(r,     c + 1, acc[mi][nj][1]);
            ep(r + 8, c,     acc[mi][nj][2]);
            ep(r + 8, c + 1, acc[mi][nj][3]);
        }
}

// ---------------- warp LayerNorm over a 768-row ----------------
__device__ __forceinline__ void ln_row(const float* __restrict__ x,
                                       const float* __restrict__ g,
                                       const float* __restrict__ b,
                                       float* __restrict__ o) {
    int lane = threadIdx.x & 31;
    float v[24];
    float s = 0.f, q = 0.f;
    #pragma unroll
    for (int i = 0; i < 24; i++) {
        v[i] = x[lane + 32 * i];
        s += v[i];
        q += v[i] * v[i];
    }
    #pragma unroll
    for (int off = 16; off; off >>= 1) {
        s += __shfl_xor_sync(0xffffffffu, s, off);
        q += __shfl_xor_sync(0xffffffffu, q, off);
    }
    float mu  = s * (1.f / 768.f);
    float inv = rsqrtf(q * (1.f / 768.f) - mu * mu + 1e-5f);
    #pragma unroll
    for (int i = 0; i < 24; i++) {
        int idx = lane + 32 * i;
        o[idx] = (v[i] - mu) * inv * g[idx] + b[idx];
    }
}

// ---------------- The single persistent kernel ----------------
extern __shared__ __align__(16) uint32_t dynsm[];

__global__ void __launch_bounds__(TPB, 3) fused_kernel(Params P) {
    uint32_t* sm = dynsm;
    const uint32_t saBase = (uint32_t)__cvta_generic_to_shared(dynsm);
    const int nb = P.nb;
    const int bid = blockIdx.x;
    const int wglob = bid * 8 + (threadIdx.x >> 5);
    const int nwarp = nb * 8;
    const int lane32 = threadIdx.x & 31;
    const int nth = nwarp * 32;
    const int gt = wglob * 32 + lane32;

    // ---- S0: LayerNorms ----
    for (int r = wglob; r < 1280; r += nwarp) {
        if (r < 256) ln_row(P.recv + r * 768, P.lnrg, P.lnrb, g_r + r * 768);
        else {
            int rr = r - 256;
            ln_row(P.send + rr * 768, P.lnsg, P.lnsb, g_s + rr * 768);
        }
    }
    grid_bar(nb);

    // ---- S1: 4 modulation GEMMs, K split x2 (K=192 -> 12 steps): 176 tiles ----
    for (int tt = bid; tt < 176; tt += nb) {
        const float* W; float* O; int N, lt, kp;
        if (tt < 144) {
            int sel = tt / 48, r = tt % 48;
            kp = r / 24; lt = r % 24; N = 768;
            W = sel == 0 ? P.Wmq : (sel == 1 ? P.Wmk : P.Wmv);
            O = (sel == 0 ? g_mqp : (sel == 1 ? g_mkp : g_mvp)) + kp * 196608;
        } else {
            int r = tt - 144;
            kp = r / 16; lt = r % 16; N = 512;
            W = P.Wme; O = g_mep + kp * 131072;
        }
        int m0 = (lt & 1) * 128, n0 = (lt >> 1) * 64, kb = kp * 192;
        gemm_cp<false>(192, sm, saBase,
            [&](int m, int k) { return &P.codes[(m0 + m) * 384 + kb + k]; },
            [&](int k, int n) { return &W[(kb + k) * N + n0 + n]; },
            [&](int m, int n, float a) { O[(long)(m0 + m) * N + n0 + n] = a; });
    }
    grid_bar(nb);

    // ---- S1b: rq = r * (1 + mqp0 + mqp1) ----
    for (int i = gt; i < 49152; i += nth) {
        long idx = (long)i * 4;
        float4 a = ld4(&g_mqp[idx]), b = ld4(&g_mqp[196608 + idx]), r = ld4(&g_r[idx]);
        float4 o;
        o.x = r.x * (1.f + a.x + b.x); o.y = r.y * (1.f + a.y + b.y);
        o.z = r.z * (1.f + a.z + b.z); o.w = r.w * (1.f + a.w + b.w);
        *(float4*)&g_rq[idx] = o;
    }
    grid_bar(nb);

    // ---- S2: q partials, K split x8 (K=96 -> 6 steps): 128 tiles ----
    for (int tt = bid; tt < 128; tt += nb) {
        int kp = tt >> 4, lt = tt & 15;
        int m0 = (lt & 1) * 128, n0 = (lt >> 1) * 64, kb = kp * 96;
        gemm_cp<false>(96, sm, saBase,
            [&](int m, int k) { return &g_rq[(m0 + m) * 768 + kb + k]; },
            [&](int k, int n) { return &P.Wq[(kb + k) * 512 + n0 + n]; },
            [&](int m, int n, float a) { g_qp[kp * QP + (m0 + m) * 512 + n0 + n] = a; });
    }
    grid_bar(nb);

    // ---- S2b: q = sum(8 partials)+bq ; qbk = q_h . bk_h ----
    for (int w = wglob; w < 2048; w += nwarp) {
        int bu = w >> 3, h = w & 7;
        int base = bu * 512 + h * 64;
        int c0 = h * 64 + lane32, c1 = c0 + 32;
        float q0 = P.bq[c0], q1 = P.bq[c1];
        #pragma unroll
        for (int p = 0; p < 8; p++) {
            q0 += g_qp[p * QP + base + lane32];
            q1 += g_qp[p * QP + base + lane32 + 32];
        }
        g_q[base + lane32] = q0;
        g_q[base + lane32 + 32] = q1;
        float s = q0 * P.bk[c0] + q1 * P.bk[c1];
        #pragma unroll
        for (int off = 16; off; off >>= 1) s += __shfl_xor_sync(0xffffffffu, s, off);
        if (lane32 == 0) g_qbk[bu * 8 + h] = s;
    }
    grid_bar(nb);

    // ---- S3: Ak = (Wk_h^T q_h)*(1+mk0+mk1)  per-head NT, K=64 -> 4 steps: 192 tiles ----
    for (int tt = bid; tt < 192; tt += nb) {
        int h = tt / 24, lt = tt % 24;
        int m0 = (lt & 1) * 128, n0 = (lt >> 1) * 64;
        gemm_cp<true>(64, sm, saBase,
            [&](int m, int k) { return &g_q[(m0 + m) * 512 + h * 64 + k]; },
            [&](int n, int k) { return &P.Wk[(n0 + n) * 512 + h * 64 + k]; },
            [&](int m, int n, float a) {
                int mg = m0 + m; int b = mg >> 6, u = mg & 63;
                long mi = (long)mg * 768 + n0 + n;
                g_Ak[b * 393216 + (h * 64 + u) * 768 + n0 + n] =
                    a * (1.f + g_mkp[mi] + g_mkp[196608 + mi]);
            });
    }
    grid_bar(nb);

    // ---- S4: score partials, K split x3 (K=256 -> 16 steps): 192 tiles ----
    for (int tt = bid; tt < 192; tt += nb) {
        int kp = tt / 64, r = tt % 64;
        int b = r >> 4, l2 = r & 15;
        int m0 = (l2 & 3) * 128, n0 = (l2 >> 2) * 64, kb = kp * 256;
        gemm_cp<true>(256, sm, saBase,
            [&](int m, int k) { return &g_Ak[b * 393216 + (m0 + m) * 768 + kb + k]; },
            [&](int n, int k) { return &g_s[(b * 256 + n0 + n) * 768 + kb + k]; },
            [&](int m, int n, float a) {
                g_wp[kp * WP + b * 131072 + (m0 + m) * 256 + n0 + n] = a;
            });
    }
    grid_bar(nb);

    // ---- S5: softmax( (wp0+wp1+wp2+qbk)/8 ) -> g_w ----
    for (int r = wglob; r < 2048; r += nwarp) {
        int b = r >> 9, mg = r & 511;
        int h = mg >> 6, u = mg & 63;
        float qb = g_qbk[(b * 64 + u) * 8 + h];
        long base = (long)b * 131072 + (long)mg * 256;
        float v[8], mx = -1e30f;
        #pragma unroll
        for (int i = 0; i < 8; i++) {
            long idx = base + lane32 + 32 * i;
            v[i] = (g_wp[idx] + g_wp[WP + idx] + g_wp[2 * WP + idx] + qb) * 0.125f;
            mx = fmaxf(mx, v[i]);
        }
        #pragma unroll
        for (int off = 16; off; off >>= 1) mx = fmaxf(mx, __shfl_xor_sync(0xffffffffu, mx, off));
        float smv = 0.f;
        #pragma unroll
        for (int i = 0; i < 8; i++) { v[i] = expf(v[i] - mx); smv += v[i]; }
        #pragma unroll
        for (int off = 16; off; off >>= 1) smv += __shfl_xor_sync(0xffffffffu, smv, off);
        float inv = 1.f / smv;
        #pragma unroll
        for (int i = 0; i < 8; i++) g_w[base + lane32 + 32 * i] = v[i] * inv;
    }
    grid_bar(nb);

    // ---- S6: Tm = (w @ s)*(1+mv0+mv1), per-head remap: K=256 -> 16 steps: 192 tiles ----
    for (int tt = bid; tt < 192; tt += nb) {
        int b = tt / 48, lt = tt % 48;
        int m0 = (lt & 3) * 128, n0 = (lt >> 2) * 64;
        gemm_cp<false>(256, sm, saBase,
            [&](int m, int k) { return &g_w[b * 131072 + (m0 + m) * 256 + k]; },
            [&](int k, int n) { return &g_s[(b * 256 + k) * 768 + n0 + n]; },
            [&](int m, int n, float a) {
                int mg = m0 + m; int h = mg >> 6, u = mg & 63; int bu = b * 64 + u;
                long mi = (long)bu * 768 + n0 + n;
                g_Tm[(h * 256 + bu) * 768 + n0 + n] =
                    a * (1.f + g_mvp[mi] + g_mvp[196608 + mi]);
            });
    }
    grid_bar(nb);

    // ---- S7: msg partials = Tm_h @ Wv_h, K split x8 (K=96 -> 6 steps): 128 tiles ----
    for (int tt = bid; tt < 128; tt += nb) {
        int kp = tt >> 4, lt = tt & 15;
        int h = lt >> 1, m0 = (lt & 1) * 128, kb = kp * 96;
        gemm_cp<false>(96, sm, saBase,
            [&](int m, int k) { return &g_Tm[(h * 256 + m0 + m) * 768 + kb + k]; },
            [&](int k, int n) { return &P.Wv[(kb + k) * 512 + h * 64 + n]; },
            [&](int m, int n, float a) {
                g_qp[kp * QP + (m0 + m) * 512 + h * 64 + n] = a;
            });
    }
    grid_bar(nb);

    // ---- S7b: msg = (sum(8 partials)+bv)*(1+me0+me1) ----
    for (int i = gt; i < 32768; i += nth) {
        long idx = (long)i * 4;
        int c = (int)(idx & 511);
        float4 acc = ld4(&P.bv[c]);
        #pragma unroll
        for (int p = 0; p < 8; p++) {
            float4 v = ld4(&g_qp[p * QP + idx]);
            acc.x += v.x; acc.y += v.y; acc.z += v.z; acc.w += v.w;
        }
        float4 m0 = ld4(&g_mep[idx]), m1 = ld4(&g_mep[131072 + idx]);
        float4 o;
        o.x = acc.x * (1.f + m0.x + m1.x); o.y = acc.y * (1.f + m0.y + m1.y);
        o.z = acc.z * (1.f + m0.z + m1.z); o.w = acc.w * (1.f + m0.w + m1.w);
        *(float4*)&g_msg[idx] = o;
    }
    grid_bar(nb);

    // ---- S8: out partials = msg @ We, K split x8 (K=64 -> 4 steps): 192 tiles ----
    for (int tt = bid; tt < 192; tt += nb) {
        int kp = tt / 24, lt = tt % 24;
        int m0 = (lt & 1) * 128, n0 = (lt >> 1) * 64, kb = kp * 64;
        gemm_cp<false>(64, sm, saBase,
            [&](int m, int k) { return &g_msg[(m0 + m) * 512 + kb + k]; },
            [&](int k, int n) { return &P.We[(kb + k) * 768 + n0 + n]; },
            [&](int m, int n, float a) {
                g_wp[kp * OP + (m0 + m) * 768 + n0 + n] = a;
            });
    }
    grid_bar(nb);

    // ---- S9: out = recv + (sum(8 partials)+be)*gamma ----
    for (int i = gt; i < 49152; i += nth) {
        long idx = (long)i * 4;
        int c = (int)(idx % 768);
        float4 acc = ld4(&P.be[c]);
        #pragma unroll
        for (int p = 0; p < 8; p++) {
            float4 v = ld4(&g_wp[p * OP + idx]);
            acc.x += v.x; acc.y += v.y; acc.z += v.z; acc.w += v.w;
        }
        float4 ga = ld4(&P.gamma[c]);
        float4 rv = ld4(&P.recv[idx]);
        float4 o;
        o.x = rv.x + acc.x * ga.x; o.y = rv.y + acc.y * ga.y;
        o.z = rv.z + acc.z * ga.z; o.w = rv.w + acc.w * ga.w;
        *(float4*)&P.out[idx] = o;
    }
}

// ---------------- Host launcher ----------------
extern "C" void kernel_launch(void* const* d_in, const int* in_sizes, int n_in,
                              void* d_out, int out_size) {
    (void)in_sizes; (void)n_in; (void)out_size;
    Params P;
    P.recv  = (const float*)d_in[0];
    P.codes = (const float*)d_in[1];
    P.send  = (const float*)d_in[2];
    P.lnrg  = (const float*)d_in[3];
    P.lnrb  = (const float*)d_in[4];
    P.lnsg  = (const float*)d_in[5];
    P.lnsb  = (const float*)d_in[6];
    P.Wq  = (const float*)d_in[7];
    P.bq  = (const float*)d_in[8];
    P.Wmq = (const float*)d_in[9];
    P.Wk  = (const float*)d_in[10];
    P.bk  = (const float*)d_in[11];
    P.Wmk = (const float*)d_in[12];
    P.Wv  = (const float*)d_in[13];
    P.bv  = (const float*)d_in[14];
    P.Wmv = (const float*)d_in[15];
    P.We  = (const float*)d_in[16];
    P.be  = (const float*)d_in[17];
    P.Wme = (const float*)d_in[18];
    P.gamma = (const float*)d_in[19];
    P.out = (float*)d_out;

    cudaFuncSetAttribute(fused_kernel,
                         cudaFuncAttributeMaxDynamicSharedMemorySize, DYNSMEM);

    int occ = 0;
    cudaOccupancyMaxActiveBlocksPerMultiprocessor(&occ, fused_kernel, TPB, DYNSMEM);
    if (occ < 1) occ = 1;
    int dev = 0;
    cudaGetDevice(&dev);
    int sms = 0;
    cudaDeviceGetAttribute(&sms, cudaDevAttrMultiProcessorCount, dev);
    if (sms < 1) sms = 1;
    int nb = occ * sms;
    if (nb > 1024) nb = 1024;
    P.nb = nb;

    fused_kernel<<<nb, TPB, DYNSMEM>>>(P);
}

// round 15
// speedup vs baseline: 1.0406x; 1.0039x over previous
#include <cuda_runtime.h>
#include <cstdint>

#define TPB 512
#define SAS 20              // A row stride (16 + 4 pad) words
#define ABUFW 2560          // 128*20 words per A stage
#define BBUFW 2560          // covers all B modes
#define ASPAN 10240         // 4*ABUFW
#define DYNSMEM 81920       // (ASPAN + 4*BBUFW)*4 bytes

// B=4, U=64, V=256, DIM=768, CODE=384, INNER=512, HEADS=8, HD=64

struct Params {
    const float *recv, *codes, *send;
    const float *lnrg, *lnrb, *lnsg, *lnsb;
    const float *Wq, *bq, *Wmq, *Wk, *bk, *Wmk;
    const float *Wv, *bv, *Wmv, *We, *be, *Wme, *gamma;
    float* out;
    int nb;
};

// ---------------- Scratch (device globals; no allocs) ----------------
__device__ __align__(16) float g_r  [256 * 768];
__device__ __align__(16) float g_s  [1024 * 768];
__device__ __align__(16) float g_rq [256 * 768];
__device__ __align__(16) float g_mqp[3 * 196608];
__device__ __align__(16) float g_mkp[3 * 196608];
__device__ __align__(16) float g_mvp[3 * 196608];
__device__ __align__(16) float g_mep[3 * 131072];
__device__ __align__(16) float g_q  [256 * 512];
__device__ __align__(16) float g_qbk[256 * 8];
__device__ __align__(16) float g_Ak [4 * 512 * 768];
__device__ __align__(16) float g_w  [4 * 512 * 256];
__device__ __align__(16) float g_Tm [8 * 256 * 768];
__device__ __align__(16) float g_msg[256 * 512];
#define QP 131072
#define WP 524288
#define OP 196608
__device__ __align__(16) float g_qp[16 * QP];   // q partials (16); msg partials (8)
__device__ __align__(16) float g_wp[4 * WP];    // score partials (4); out partials (8*OP)

__device__ unsigned g_barcnt = 0;
__device__ unsigned g_bargen = 0;

__device__ __forceinline__ void grid_bar(int nb) {
    __syncthreads();
    if (threadIdx.x == 0) {
        __threadfence();
        unsigned gen = *(volatile unsigned*)&g_bargen;
        unsigned t = atomicAdd(&g_barcnt, 1u);
        if (t == (unsigned)(nb - 1)) {
            atomicExch(&g_barcnt, 0u);
            __threadfence();
            atomicExch(&g_bargen, gen + 1u);
        } else {
            while (*(volatile unsigned*)&g_bargen == gen) { __nanosleep(32); }
        }
        __threadfence();
    }
    __syncthreads();
}

// ---------------- mma + cp.async helpers ----------------
__device__ __forceinline__ void mma8(float* c, const uint32_t* a, const uint32_t* b) {
    asm volatile(
        "mma.sync.aligned.m16n8k8.row.col.f32.tf32.tf32.f32 "
        "{%0,%1,%2,%3}, {%4,%5,%6,%7}, {%8,%9}, {%0,%1,%2,%3};"
        : "+f"(c[0]), "+f"(c[1]), "+f"(c[2]), "+f"(c[3])
        : "r"(a[0]), "r"(a[1]), "r"(a[2]), "r"(a[3]), "r"(b[0]), "r"(b[1]));
}
__device__ __forceinline__ uint32_t tfr(uint32_t raw) {
    uint32_t u;
    asm("cvt.rna.tf32.f32 %0, %1;" : "=r"(u) : "f"(__uint_as_float(raw)));
    return u;
}
__device__ __forceinline__ void cp16(uint32_t dst, const float* src) {
    asm volatile("cp.async.cg.shared.global [%0], [%1], 16;\n"
                 :: "r"(dst), "l"(src) : "memory");
}
__device__ __forceinline__ void cp_commit() {
    asm volatile("cp.async.commit_group;\n" ::: "memory");
}
__device__ __forceinline__ void cp_wait2() {
    asm volatile("cp.async.wait_group 2;\n" ::: "memory");
}
__device__ __forceinline__ float4 ld4(const float* p) { return *(const float4*)p; }

// ---- block 128xNTILE tf32 GEMM, 512 threads, 4-stage cp.async pipeline ----
// C(m,n) = sum_k A(m,k)*B(k,n); m in [0,128), n in [0,NTILE); K%16==0.
// la(m,k)->ptr A(m, k..k+3).
// BT=false: lb(k,n)->ptr B(k, n..n+3); BT=true: lb(n,k)->ptr B(n-th row, k..k+3).
template<bool BT, int NTILE, class LA, class LB, class EP>
__device__ __forceinline__ void gemm_cp(int K, uint32_t* sm, uint32_t saBase,
                                        LA la, LB lb, EP ep) {
    constexpr int NJ = NTILE / 32;                 // 8-col frag groups per warp
    constexpr int SB = BT ? 20 : (NTILE + 8);      // B smem row stride (words)
    const int tid = threadIdx.x;
    const int l = tid & 31, g = l >> 2, t = l & 3;
    const int wid = tid >> 5;                      // 0..15
    const int wm0 = (wid >> 2) * 32, wn0 = (wid & 3) * (NTILE / 4);
    const int ns = K / 16;

    const int ar = tid >> 2, ac = (tid & 3) * 4;   // A fill (all 512)
    const bool bact = tid < NTILE * 4;             // B fill active threads
    int bk = 0, bn = 0, btn = 0, btk = 0;
    if (BT) { btn = tid >> 2; btk = (tid & 3) * 4; }
    else    { bk = tid / (NTILE / 4); bn = (tid % (NTILE / 4)) * 4; }

    const uint32_t dA = saBase + (uint32_t)(ar * SAS + ac) * 4u;
    const uint32_t bbase = saBase + (uint32_t)ASPAN * 4u;
    const uint32_t dB = BT ? bbase + (uint32_t)(btn * 20 + btk) * 4u
                           : bbase + (uint32_t)(bk * SB + bn) * 4u;

    auto issue = [&](int s) {
        int buf = s & 3;
        int k0 = s * 16;
        cp16(dA + buf * (ABUFW * 4u), la(ar, k0 + ac));
        if (bact) cp16(dB + buf * (BBUFW * 4u), BT ? lb(btn, k0 + btk) : lb(k0 + bk, bn));
        cp_commit();
    };

    float acc[2][NJ][4];
    #pragma unroll
    for (int i = 0; i < 2; i++)
        #pragma unroll
        for (int j = 0; j < NJ; j++)
            #pragma unroll
            for (int e = 0; e < 4; e++) acc[i][j][e] = 0.f;

    issue(0); issue(1); issue(2);
    cp_wait2();
    __syncthreads();

    for (int s = 0; s < ns; s++) {
        if (s + 3 < ns) issue(s + 3); else cp_commit();
        const uint32_t* __restrict__ A = sm + (s & 3) * ABUFW;
        const uint32_t* __restrict__ B = sm + ASPAN + (s & 3) * BBUFW;
        #pragma unroll
        for (int kk = 0; kk < 16; kk += 8) {
            uint32_t af[2][4], bf[NJ][2];
            #pragma unroll
            for (int mi = 0; mi < 2; mi++) {
                int mb = wm0 + mi * 16;
                af[mi][0] = tfr(A[(mb + g) * SAS + kk + t]);
                af[mi][1] = tfr(A[(mb + 8 + g) * SAS + kk + t]);
                af[mi][2] = tfr(A[(mb + g) * SAS + kk + t + 4]);
                af[mi][3] = tfr(A[(mb + 8 + g) * SAS + kk + t + 4]);
            }
            #pragma unroll
            for (int nj = 0; nj < NJ; nj++) {
                int nn = wn0 + nj * 8 + g;
                if (BT) {
                    bf[nj][0] = tfr(B[nn * 20 + kk + t]);
                    bf[nj][1] = tfr(B[nn * 20 + kk + t + 4]);
                } else {
                    bf[nj][0] = tfr(B[(kk + t) * SB + nn]);
                    bf[nj][1] = tfr(B[(kk + t + 4) * SB + nn]);
                }
            }
            #pragma unroll
            for (int mi = 0; mi < 2; mi++)
                #pragma unroll
                for (int nj = 0; nj < NJ; nj++)
                    mma8(acc[mi][nj], af[mi], bf[nj]);
        }
        cp_wait2();
        __syncthreads();
    }

    #pragma unroll
    for (int mi = 0; mi < 2; mi++)
        #pragma unroll
        for (int nj = 0; nj < NJ; nj++) {
            int r = wm0 + mi * 16 + g, c = wn0 + nj * 8 + 2 * t;
            ep(r,     c,     acc[mi][nj][0]);
            ep(r,     c + 1, acc[mi][nj][1]);
            ep(r + 8, c,     acc[mi][nj][2]);
            ep(r + 8, c + 1, acc[mi][nj][3]);
        }
}

// ---------------- warp LayerNorm over a 768-row ----------------
__device__ __forceinline__ void ln_row(const float* __restrict__ x,
                                       const float* __restrict__ g,
                                       const float* __restrict__ b,
                                       float* __restrict__ o) {
    int lane = threadIdx.x & 31;
    float v[24];
    float s = 0.f, q = 0.f;
    #pragma unroll
    for (int i = 0; i < 24; i++) {
        v[i] = x[lane + 32 * i];
        s += v[i];
        q += v[i] * v[i];
    }
    #pragma unroll
    for (int off = 16; off; off >>= 1) {
        s += __shfl_xor_sync(0xffffffffu, s, off);
        q += __shfl_xor_sync(0xffffffffu, q, off);
    }
    float mu  = s * (1.f / 768.f);
    float inv = rsqrtf(q * (1.f / 768.f) - mu * mu + 1e-5f);
    #pragma unroll
    for (int i = 0; i < 24; i++) {
        int idx = lane + 32 * i;
        o[idx] = (v[i] - mu) * inv * g[idx] + b[idx];
    }
}

// ---------------- The single persistent kernel: 1 block/SM, 512 threads ----
extern __shared__ __align__(16) uint32_t dynsm[];

__global__ void __launch_bounds__(TPB, 1) fused_kernel(Params P) {
    uint32_t* sm = dynsm;
    const uint32_t saBase = (uint32_t)__cvta_generic_to_shared(dynsm);
    const int nb = P.nb;
    const int bid = blockIdx.x;
    const int wglob = bid * 16 + (threadIdx.x >> 5);
    const int nwarp = nb * 16;
    const int lane32 = threadIdx.x & 31;
    const int nth = nwarp * 32;
    const int gt = wglob * 32 + lane32;

    // ---- S0: LayerNorms ----
    for (int r = wglob; r < 1280; r += nwarp) {
        if (r < 256) ln_row(P.recv + r * 768, P.lnrg, P.lnrb, g_r + r * 768);
        else {
            int rr = r - 256;
            ln_row(P.send + rr * 768, P.lnsg, P.lnsb, g_s + rr * 768);
        }
    }
    grid_bar(nb);

    // ---- S1: 4 modulation GEMMs, K split x3 (K=128 -> 8 steps): 132 tiles ----
    for (int tt = bid; tt < 132; tt += nb) {
        if (tt < 108) {
            int sel = tt / 36, r = tt % 36;
            int kp = r / 12, lt = r % 12;
            const float* W = sel == 0 ? P.Wmq : (sel == 1 ? P.Wmk : P.Wmv);
            float* O = (sel == 0 ? g_mqp : (sel == 1 ? g_mkp : g_mvp)) + kp * 196608;
            int m0 = (lt % 2) * 128, n0 = (lt / 2) * 128, kb = kp * 128;
            gemm_cp<false, 128>(128, sm, saBase,
                [&](int m, int k) { return &P.codes[(m0 + m) * 384 + kb + k]; },
                [&](int k, int n) { return &W[(kb + k) * 768 + n0 + n]; },
                [&](int m, int n, float a) { O[(long)(m0 + m) * 768 + n0 + n] = a; });
        } else {
            int r = tt - 108;
            int kp = r / 8, lt = r % 8;
            float* O = g_mep + kp * 131072;
            int m0 = (lt & 1) * 128, n0 = (lt >> 1) * 128, kb = kp * 128;
            gemm_cp<false, 128>(128, sm, saBase,
                [&](int m, int k) { return &P.codes[(m0 + m) * 384 + kb + k]; },
                [&](int k, int n) { return &P.Wme[(kb + k) * 512 + n0 + n]; },
                [&](int m, int n, float a) { O[(long)(m0 + m) * 512 + n0 + n] = a; });
        }
    }
    grid_bar(nb);

    // ---- S1b: rq = r * (1 + mqp0+mqp1+mqp2) ----
    for (int i = gt; i < 49152; i += nth) {
        long idx = (long)i * 4;
        float4 a = ld4(&g_mqp[idx]), b = ld4(&g_mqp[196608 + idx]);
        float4 c = ld4(&g_mqp[2 * 196608 + idx]), r = ld4(&g_r[idx]);
        float4 o;
        o.x = r.x * (1.f + a.x + b.x + c.x); o.y = r.y * (1.f + a.y + b.y + c.y);
        o.z = r.z * (1.f + a.z + b.z + c.z); o.w = r.w * (1.f + a.w + b.w + c.w);
        *(float4*)&g_rq[idx] = o;
    }
    grid_bar(nb);

    // ---- S2: q partials, K split x16 (K=48 -> 3 steps): 128 tiles ----
    for (int tt = bid; tt < 128; tt += nb) {
        int kp = tt >> 3, lt = tt & 7;
        int m0 = (lt & 1) * 128, n0 = (lt >> 1) * 128, kb = kp * 48;
        gemm_cp<false, 128>(48, sm, saBase,
            [&](int m, int k) { return &g_rq[(m0 + m) * 768 + kb + k]; },
            [&](int k, int n) { return &P.Wq[(kb + k) * 512 + n0 + n]; },
            [&](int m, int n, float a) { g_qp[kp * QP + (m0 + m) * 512 + n0 + n] = a; });
    }
    grid_bar(nb);

    // ---- S2b: q = sum(16 partials)+bq ; qbk = q_h . bk_h ----
    for (int w = wglob; w < 2048; w += nwarp) {
        int bu = w >> 3, h = w & 7;
        int base = bu * 512 + h * 64;
        int c0 = h * 64 + lane32, c1 = c0 + 32;
        float q0 = P.bq[c0], q1 = P.bq[c1];
        #pragma unroll
        for (int p = 0; p < 16; p++) {
            q0 += g_qp[p * QP + base + lane32];
            q1 += g_qp[p * QP + base + lane32 + 32];
        }
        g_q[base + lane32] = q0;
        g_q[base + lane32 + 32] = q1;
        float s = q0 * P.bk[c0] + q1 * P.bk[c1];
        #pragma unroll
        for (int off = 16; off; off >>= 1) s += __shfl_xor_sync(0xffffffffu, s, off);
        if (lane32 == 0) g_qbk[bu * 8 + h] = s;
    }
    grid_bar(nb);

    // ---- S3: Ak = (Wk_h^T q_h)*(1+mk)  per-head NT, K=64 -> 4 steps: 96 tiles ----
    for (int tt = bid; tt < 96; tt += nb) {
        int h = tt / 12, lt = tt % 12;
        int m0 = (lt & 1) * 128, n0 = (lt >> 1) * 128;
        gemm_cp<true, 128>(64, sm, saBase,
            [&](int m, int k) { return &g_q[(m0 + m) * 512 + h * 64 + k]; },
            [&](int n, int k) { return &P.Wk[(n0 + n) * 512 + h * 64 + k]; },
            [&](int m, int n, float a) {
                int mg = m0 + m; int b = mg >> 6, u = mg & 63;
                long mi = (long)mg * 768 + n0 + n;
                g_Ak[b * 393216 + (h * 64 + u) * 768 + n0 + n] =
                    a * (1.f + g_mkp[mi] + g_mkp[196608 + mi] + g_mkp[2 * 196608 + mi]);
            });
    }
    grid_bar(nb);

    // ---- S4: score partials, K split x4 (K=192 -> 12 steps): 128 tiles ----
    for (int tt = bid; tt < 128; tt += nb) {
        int kp = tt >> 5, r = tt & 31;
        int b = r >> 3, l2 = r & 7;
        int m0 = (l2 & 3) * 128, n0 = (l2 >> 2) * 128, kb = kp * 192;
        gemm_cp<true, 128>(192, sm, saBase,
            [&](int m, int k) { return &g_Ak[b * 393216 + (m0 + m) * 768 + kb + k]; },
            [&](int n, int k) { return &g_s[(b * 256 + n0 + n) * 768 + kb + k]; },
            [&](int m, int n, float a) {
                g_wp[kp * WP + b * 131072 + (m0 + m) * 256 + n0 + n] = a;
            });
    }
    grid_bar(nb);

    // ---- S5: softmax( (wp0..wp3+qbk)/8 ) -> g_w ----
    for (int r = wglob; r < 2048; r += nwarp) {
        int b = r >> 9, mg = r & 511;
        int h = mg >> 6, u = mg & 63;
        float qb = g_qbk[(b * 64 + u) * 8 + h];
        long base = (long)b * 131072 + (long)mg * 256;
        float v[8], mx = -1e30f;
        #pragma unroll
        for (int i = 0; i < 8; i++) {
            long idx = base + lane32 + 32 * i;
            v[i] = (g_wp[idx] + g_wp[WP + idx] + g_wp[2 * WP + idx] +
                    g_wp[3 * WP + idx] + qb) * 0.125f;
            mx = fmaxf(mx, v[i]);
        }
        #pragma unroll
        for (int off = 16; off; off >>= 1) mx = fmaxf(mx, __shfl_xor_sync(0xffffffffu, mx, off));
        float smv = 0.f;
        #pragma unroll
        for (int i = 0; i < 8; i++) { v[i] = expf(v[i] - mx); smv += v[i]; }
        #pragma unroll
        for (int off = 16; off; off >>= 1) smv += __shfl_xor_sync(0xffffffffu, smv, off);
        float inv = 1.f / smv;
        #pragma unroll
        for (int i = 0; i < 8; i++) g_w[base + lane32 + 32 * i] = v[i] * inv;
    }
    grid_bar(nb);

    // ---- S6: Tm = (w @ s)*(1+mv), per-head remap: K=256 -> 16 steps: 96 tiles ----
    for (int tt = bid; tt < 96; tt += nb) {
        int b = tt / 24, lt = tt % 24;
        int m0 = (lt & 3) * 128, n0 = (lt >> 2) * 128;
        gemm_cp<false, 128>(256, sm, saBase,
            [&](int m, int k) { return &g_w[b * 131072 + (m0 + m) * 256 + k]; },
            [&](int k, int n) { return &g_s[(b * 256 + k) * 768 + n0 + n]; },
            [&](int m, int n, float a) {
                int mg = m0 + m; int h = mg >> 6, u = mg & 63; int bu = b * 64 + u;
                long mi = (long)bu * 768 + n0 + n;
                g_Tm[(h * 256 + bu) * 768 + n0 + n] =
                    a * (1.f + g_mvp[mi] + g_mvp[196608 + mi] + g_mvp[2 * 196608 + mi]);
            });
    }
    grid_bar(nb);

    // ---- S7: msg partials = Tm_h @ Wv_h, NTILE=64, K split x8 (K=96 -> 6): 128 tiles ----
    for (int tt = bid; tt < 128; tt += nb) {
        int kp = tt >> 4, lt = tt & 15;
        int h = lt >> 1, m0 = (lt & 1) * 128, kb = kp * 96;
        gemm_cp<false, 64>(96, sm, saBase,
            [&](int m, int k) { return &g_Tm[(h * 256 + m0 + m) * 768 + kb + k]; },
            [&](int k, int n) { return &P.Wv[(kb + k) * 512 + h * 64 + n]; },
            [&](int m, int n, float a) {
                g_qp[kp * QP + (m0 + m) * 512 + h * 64 + n] = a;
            });
    }
    grid_bar(nb);

    // ---- S7b: msg = (sum(8 partials)+bv)*(1+me0+me1+me2) ----
    for (int i = gt; i < 32768; i += nth) {
        long idx = (long)i * 4;
        int c = (int)(idx & 511);
        float4 acc = ld4(&P.bv[c]);
        #pragma unroll
        for (int p = 0; p < 8; p++) {
            float4 v = ld4(&g_qp[p * QP + idx]);
            acc.x += v.x; acc.y += v.y; acc.z += v.z; acc.w += v.w;
        }
        float4 m0 = ld4(&g_mep[idx]), m1 = ld4(&g_mep[131072 + idx]);
        float4 m2 = ld4(&g_mep[2 * 131072 + idx]);
        float4 o;
        o.x = acc.x * (1.f + m0.x + m1.x + m2.x); o.y = acc.y * (1.f + m0.y + m1.y + m2.y);
        o.z = acc.z * (1.f + m0.z + m1.z + m2.z); o.w = acc.w * (1.f + m0.w + m1.w + m2.w);
        *(float4*)&g_msg[idx] = o;
    }
    grid_bar(nb);

    // ---- S8: out partials = msg @ We, K split x8 (K=64 -> 4 steps): 96 tiles ----
    for (int tt = bid; tt < 96; tt += nb) {
        int kp = tt / 12, lt = tt % 12;
        int m0 = (lt & 1) * 128, n0 = (lt >> 1) * 128, kb = kp * 64;
        gemm_cp<false, 128>(64, sm, saBase,
            [&](int m, int k) { return &g_msg[(m0 + m) * 512 + kb + k]; },
            [&](int k, int n) { return &P.We[(kb + k) * 768 + n0 + n]; },
            [&](int m, int n, float a) {
                g_wp[kp * OP + (m0 + m) * 768 + n0 + n] = a;
            });
    }
    grid_bar(nb);

    // ---- S9: out = recv + (sum(8 partials)+be)*gamma ----
    for (int i = gt; i < 49152; i += nth) {
        long idx = (long)i * 4;
        int c = (int)(idx % 768);
        float4 acc = ld4(&P.be[c]);
        #pragma unroll
        for (int p = 0; p < 8; p++) {
            float4 v = ld4(&g_wp[p * OP + idx]);
            acc.x += v.x; acc.y += v.y; acc.z += v.z; acc.w += v.w;
        }
        float4 ga = ld4(&P.gamma[c]);
        float4 rv = ld4(&P.recv[idx]);
        float4 o;
        o.x = rv.x + acc.x * ga.x; o.y = rv.y + acc.y * ga.y;
        o.z = rv.z + acc.z * ga.z; o.w = rv.w + acc.w * ga.w;
        *(float4*)&P.out[idx] = o;
    }
}

// ---------------- Host launcher ----------------
extern "C" void kernel_launch(void* const* d_in, const int* in_sizes, int n_in,
                              void* d_out, int out_size) {
    (void)in_sizes; (void)n_in; (void)out_size;
    Params P;
    P.recv  = (const float*)d_in[0];
    P.codes = (const float*)d_in[1];
    P.send  = (const float*)d_in[2];
    P.lnrg  = (const float*)d_in[3];
    P.lnrb  = (const float*)d_in[4];
    P.lnsg  = (const float*)d_in[5];
    P.lnsb  = (const float*)d_in[6];
    P.Wq  = (const float*)d_in[7];
    P.bq  = (const float*)d_in[8];
    P.Wmq = (const float*)d_in[9];
    P.Wk  = (const float*)d_in[10];
    P.bk  = (const float*)d_in[11];
    P.Wmk = (const float*)d_in[12];
    P.Wv  = (const float*)d_in[13];
    P.bv  = (const float*)d_in[14];
    P.Wmv = (const float*)d_in[15];
    P.We  = (const float*)d_in[16];
    P.be  = (const float*)d_in[17];
    P.Wme = (const float*)d_in[18];
    P.gamma = (const float*)d_in[19];
    P.out = (float*)d_out;

    cudaFuncSetAttribute(fused_kernel,
                         cudaFuncAttributeMaxDynamicSharedMemorySize, DYNSMEM);

    int occ = 0;
    cudaOccupancyMaxActiveBlocksPerMultiprocessor(&occ, fused_kernel, TPB, DYNSMEM);
    if (occ < 1) occ = 1;
    int dev = 0;
    cudaGetDevice(&dev);
    int sms = 0;
    cudaDeviceGetAttribute(&sms, cudaDevAttrMultiProcessorCount, dev);
    if (sms < 1) sms = 1;
    int nb = occ * sms;
    if (nb > 1024) nb = 1024;
    P.nb = nb;

    fused_kernel<<<nb, TPB, DYNSMEM>>>(P);
}